// round 8
// baseline (speedup 1.0000x reference)
#include <cuda_runtime.h>
#include <cstdint>

#define TT 1000
#define BB 512
#define IDM 32
#define HH 64
#define NHIST 5
#define FULLM 0xffffffffu

// Kalman gains per step: layout [t][o*64 + i]
__device__ __align__(16) float g_U[TT * 192];
// per-step "correction active" flag (0 => K_t == 0, skip correction)
__device__ int g_act[TT];
// CW = C @ W_mlp  (3 x 320), Cb = C @ b_mlp (3)
__device__ __align__(16) float g_CW[3 * 320];
__device__ __align__(16) float g_Cb[4];

// ---- packed f32x2 helpers (Blackwell FFMA2 path, PTX-only) ----
__device__ __forceinline__ void fma2(unsigned long long& d,
                                     unsigned long long a,
                                     unsigned long long b) {
    asm("fma.rn.f32x2 %0, %1, %2, %0;" : "+l"(d) : "l"(a), "l"(b));
}
__device__ __forceinline__ unsigned long long pack2(float lo, float hi) {
    unsigned long long r;
    asm("mov.b64 %0, {%1, %2};" : "=l"(r) : "f"(lo), "f"(hi));
    return r;
}
__device__ __forceinline__ float2 unpack2(unsigned long long v) {
    float2 r;
    asm("mov.b64 {%0, %1}, %2;" : "=f"(r.x), "=f"(r.y) : "l"(v));
    return r;
}

// ======================================================================
// Producer: prep (CW fold) + Riccati chain -> K_t. Single block.
// Exit when max|K| <= 1e-6 (K->0 geometrically); zero-fill tail.
// ======================================================================
#define PD 66   // even => 8B-aligned float2 rows; padded => clean banks

struct PSmem {
    float A[64 * PD];
    float At[64 * PD];
    float cov[64 * PD];
    float E[64 * PD];
    float P[64 * PD];
    float Cs[192];
    float Y[64 * 3];
    float S[9];
    float Si[9];
    float U[192];
    float Up[192];
    float CP[192];
    int ctl[2];
    int done;      // 0 = continue, 1 = tail<-U (stationary), 2 = tail<-0
};

__global__ void __launch_bounds__(256, 1)
cov_kernel(const float* __restrict__ W_hh, const float* __restrict__ Cmat,
           const float* __restrict__ W_mlp, const float* __restrict__ b_mlp) {
    extern __shared__ char praw[];
    PSmem& s = *reinterpret_cast<PSmem*>(praw);
    const int tid = threadIdx.x;

    // ---- prep: CW = C @ W_mlp, Cb = C @ b_mlp, g_act init ----
    for (int idx = tid; idx < 960; idx += 256) {
        int o = idx / 320, m = idx - o * 320;
        float acc = 0.f;
        #pragma unroll 8
        for (int j = 0; j < 64; j++) acc += Cmat[o * 64 + j] * W_mlp[j * 320 + m];
        g_CW[idx] = acc;
    }
    if (tid < 3) {
        float acc = 0.f;
        for (int j = 0; j < 64; j++) acc += Cmat[tid * 64 + j] * b_mlp[j];
        g_Cb[tid] = acc;
    }
    if (tid >= 8 && tid < 8 + NHIST) g_act[tid - 8] = 0;

    for (int idx = tid; idx < 4096; idx += 256) {
        int i = idx >> 6, k = idx & 63;
        float v = W_hh[idx];
        s.A[i * PD + k]  = v;
        s.At[k * PD + i] = v;
        s.cov[i * PD + k] = (i == k) ? 1.f : 0.f;
    }
    for (int idx = tid; idx < 192; idx += 256) { s.Cs[idx] = Cmat[idx]; s.Up[idx] = 0.f; }
    if (tid < 2) s.ctl[tid] = 0;
    if (tid == 0) s.done = 0;
    __syncthreads();

    const int ty = tid >> 4;
    const int tx = tid & 15;

    for (int t = NHIST; t < TT; t++) {
        // ---- E = A @ cov  (f32x2) ----
        {
            unsigned long long c01[4] = {0, 0, 0, 0};
            unsigned long long c23[4] = {0, 0, 0, 0};
            #pragma unroll 4
            for (int k = 0; k < 64; k++) {
                unsigned long long b01 =
                    *(const unsigned long long*)&s.cov[k * PD + tx * 4];
                unsigned long long b23 =
                    *(const unsigned long long*)&s.cov[k * PD + tx * 4 + 2];
                #pragma unroll
                for (int r = 0; r < 4; r++) {
                    float av = s.A[(ty * 4 + r) * PD + k];
                    unsigned long long ap = pack2(av, av);
                    fma2(c01[r], ap, b01);
                    fma2(c23[r], ap, b23);
                }
            }
            #pragma unroll
            for (int r = 0; r < 4; r++) {
                *(float2*)&s.E[(ty * 4 + r) * PD + tx * 4]     = unpack2(c01[r]);
                *(float2*)&s.E[(ty * 4 + r) * PD + tx * 4 + 2] = unpack2(c23[r]);
            }
        }
        __syncthreads();

        // ---- P = E @ A^T ----
        {
            unsigned long long c01[4] = {0, 0, 0, 0};
            unsigned long long c23[4] = {0, 0, 0, 0};
            #pragma unroll 4
            for (int k = 0; k < 64; k++) {
                unsigned long long b01 =
                    *(const unsigned long long*)&s.At[k * PD + tx * 4];
                unsigned long long b23 =
                    *(const unsigned long long*)&s.At[k * PD + tx * 4 + 2];
                #pragma unroll
                for (int r = 0; r < 4; r++) {
                    float av = s.E[(ty * 4 + r) * PD + k];
                    unsigned long long ap = pack2(av, av);
                    fma2(c01[r], ap, b01);
                    fma2(c23[r], ap, b23);
                }
            }
            #pragma unroll
            for (int r = 0; r < 4; r++) {
                *(float2*)&s.P[(ty * 4 + r) * PD + tx * 4]     = unpack2(c01[r]);
                *(float2*)&s.P[(ty * 4 + r) * PD + tx * 4 + 2] = unpack2(c23[r]);
            }
        }
        __syncthreads();

        // ---- Y = P @ C^T (64x3) ----
        if (tid < 192) {
            int o = tid >> 6, i = tid & 63;
            float acc = 0.f;
            for (int k = 0; k < 64; k++) acc += s.P[i * PD + k] * s.Cs[o * 64 + k];
            s.Y[i * 3 + o] = acc;
        }
        __syncthreads();

        // ---- S = C @ Y + I ----
        if (tid < 9) {
            int o1 = tid / 3, o2 = tid - o1 * 3;
            float acc = (o1 == o2) ? 1.f : 0.f;
            for (int k = 0; k < 64; k++) acc += s.Cs[o1 * 64 + k] * s.Y[k * 3 + o2];
            s.S[tid] = acc;
        }
        __syncthreads();

        // ---- Si = inv(S) ----
        if (tid == 0) {
            float a = s.S[0], b = s.S[1], c = s.S[2];
            float d = s.S[3], e = s.S[4], f = s.S[5];
            float g = s.S[6], h = s.S[7], i2 = s.S[8];
            float A0 =  (e * i2 - f * h);
            float A1 = -(d * i2 - f * g);
            float A2 =  (d * h  - e * g);
            float B0 = -(b * i2 - c * h);
            float B1 =  (a * i2 - c * g);
            float B2 = -(a * h  - b * g);
            float C0 =  (b * f - c * e);
            float C1 = -(a * f - c * d);
            float C2 =  (a * e - b * d);
            float det = a * A0 + b * A1 + c * A2;
            float id = 1.f / det;
            s.Si[0] = A0 * id; s.Si[1] = B0 * id; s.Si[2] = C0 * id;
            s.Si[3] = A1 * id; s.Si[4] = B1 * id; s.Si[5] = C1 * id;
            s.Si[6] = A2 * id; s.Si[7] = B2 * id; s.Si[8] = C2 * id;
        }
        __syncthreads();

        // ---- U = Y @ Si (K), store, track magnitude + delta ----
        if (tid < 192) {
            int o = tid >> 6, i = tid & 63;
            float u = s.Y[i * 3 + 0] * s.Si[0 + o]
                    + s.Y[i * 3 + 1] * s.Si[3 + o]
                    + s.Y[i * 3 + 2] * s.Si[6 + o];
            s.U[tid] = u;
            g_U[t * 192 + tid] = u;
            float dd = fabsf(u - s.Up[tid]);
            s.Up[tid] = u;
            atomicMax(&s.ctl[0], __float_as_int(dd));
            atomicMax(&s.ctl[1], __float_as_int(fabsf(u)));
        }
        if (tid == 200) g_act[t] = 1;
        __syncthreads();

        // ---- CP = C @ P, exit decision ----
        if (tid < 192) {
            int o = tid >> 6, j = tid & 63;
            float acc = 0.f;
            for (int k = 0; k < 64; k++) acc += s.Cs[o * 64 + k] * s.P[k * PD + j];
            s.CP[tid] = acc;
        }
        if (tid == 0) {
            float md = __int_as_float(s.ctl[0]);
            float ma = __int_as_float(s.ctl[1]);
            if (ma <= 1e-6f)            s.done = 2;  // K negligible: tail = h_obs
            else if (md <= 1e-6f * ma)  s.done = 1;  // K stationary (nonzero)
            s.ctl[0] = 0; s.ctl[1] = 0;
        }
        __syncthreads();

        // ---- cov = P - U^T CP ----
        for (int e = tid; e < 4096; e += 256) {
            int i = e >> 6, j = e & 63;
            s.cov[i * PD + j] = s.P[i * PD + j]
                - (s.U[i]       * s.CP[j]
                 + s.U[64 + i]  * s.CP[64 + j]
                 + s.U[128 + i] * s.CP[128 + j]);
        }
        __syncthreads();

        if (s.done) {
            const int dz = (s.done == 2);
            for (int tt = t + 1; tt < TT; tt++) {
                for (int idx = tid; idx < 192; idx += 256)
                    g_U[tt * 192 + idx] = dz ? 0.f : s.U[idx];
                if (tid == 200) g_act[tt] = dz ? 0 : 1;
            }
            break;
        }
    }
}

// ======================================================================
// Consumer: block = 64 threads = 1 batch row, 2 warps split the k-dim.
// Warp w: W_hh k in [32w,32w+32), W_ih k in [16w,16w+16). Partials meet
// in parity-double-buffered smem; both warps add both partials in the
// SAME order -> bit-identical replicated h. One bar per step.
// ======================================================================
struct CSmem {
    float Wih[32 * 64];     // [k][j] = W_ih[j][k]
    float Whh[64 * 64];     // [k][j] = W_hh[j][k]
    float CW[3 * 320];      // [o][m]
    float2 red[2][2][32];   // [parity][warp][lane]
};

__global__ void __launch_bounds__(64, 1)
seq_kernel(const float* __restrict__ x,
           const float* __restrict__ W_ih, const float* __restrict__ b_ih,
           const float* __restrict__ W_hh, const float* __restrict__ b_hh,
           const float* __restrict__ C,
           float* __restrict__ out, float* __restrict__ hlast) {
    extern __shared__ char craw[];
    CSmem& s = *reinterpret_cast<CSmem*>(craw);
    const int tid  = threadIdx.x;
    const int w    = tid >> 5;       // warp 0/1: k-half
    const int lane = tid & 31;
    const int j0   = lane * 2;
    const int row  = blockIdx.x;
    const int kb   = 16 * w;         // Wih k base
    const int hb   = 32 * w;         // Whh k base

    for (int idx = tid; idx < 2048; idx += 64) {
        int k = idx >> 6, j = idx & 63; s.Wih[idx] = W_ih[j * IDM + k];
    }
    for (int idx = tid; idx < 4096; idx += 64) {
        int k = idx >> 6, j = idx & 63; s.Whh[idx] = W_hh[j * HH + k];
    }
    for (int idx = tid; idx < 960; idx += 64) s.CW[idx] = g_CW[idx];
    __syncthreads();

    // bias only in warp 0's partial (added once)
    const float ab0 = (w == 0) ? (__ldg(&b_ih[j0])     + __ldg(&b_hh[j0]))     : 0.f;
    const float ab1 = (w == 0) ? (__ldg(&b_ih[j0 + 1]) + __ldg(&b_hh[j0 + 1])) : 0.f;
    const float cb0 = g_Cb[0], cb1 = g_Cb[1], cb2 = g_Cb[2];
    const float c0a = __ldg(&C[j0]),       c0b = __ldg(&C[j0 + 1]);
    const float c1a = __ldg(&C[64 + j0]),  c1b = __ldg(&C[64 + j0 + 1]);
    const float c2a = __ldg(&C[128 + j0]), c2b = __ldg(&C[128 + j0 + 1]);

    float h0 = 0.f, h1 = 0.f;           // replicated in both warps
    float hh[NHIST][2];
    #pragma unroll
    for (int i = 0; i < NHIST; i++) { hh[i][0] = 0.f; hh[i][1] = 0.f; }

    // software pipeline: x 2-deep, act 2-deep, K 1-deep
    float xc = x[(size_t)row * IDM + lane];
    float xn = x[((size_t)1 * BB + row) * IDM + lane];
    int actc = 0, actn = 0;
    float2 kc0 = make_float2(0.f, 0.f), kc1 = kc0, kc2 = kc0;
    int par = 0;

    for (int t = 0; t < TT; t++) {
        // prefetch x[t+2], act[t+2], K[t+1]
        float xn2 = 0.f; int actn2 = 0;
        if (t + 2 < TT) {
            xn2   = x[((size_t)(t + 2) * BB + row) * IDM + lane];
            actn2 = g_act[t + 2];
        }
        float2 kn0 = make_float2(0.f, 0.f), kn1 = kn0, kn2 = kn0;
        if (actn) {
            const float* Ut = &g_U[(size_t)(t + 1) * 192];
            kn0 = *(const float2*)&Ut[j0];
            kn1 = *(const float2*)&Ut[64 + j0];
            kn2 = *(const float2*)&Ut[128 + j0];
        }

        // ---- half-GEMV partials for this warp's k range ----
        float A0 = ab0, A1 = 0.f, A2 = 0.f, A3 = 0.f;
        float B0 = ab1, B1 = 0.f, B2 = 0.f, B3 = 0.f;
        #pragma unroll
        for (int kk = 0; kk < 16; kk += 4) {
            int k = kb + kk;
            float x0 = __shfl_sync(FULLM, xc, k);
            float x1 = __shfl_sync(FULLM, xc, k + 1);
            float x2 = __shfl_sync(FULLM, xc, k + 2);
            float x3 = __shfl_sync(FULLM, xc, k + 3);
            float2 w0 = *(const float2*)&s.Wih[(k + 0) * HH + j0];
            float2 w1 = *(const float2*)&s.Wih[(k + 1) * HH + j0];
            float2 w2 = *(const float2*)&s.Wih[(k + 2) * HH + j0];
            float2 w3 = *(const float2*)&s.Wih[(k + 3) * HH + j0];
            A0 += x0 * w0.x; B0 += x0 * w0.y;
            A1 += x1 * w1.x; B1 += x1 * w1.y;
            A2 += x2 * w2.x; B2 += x2 * w2.y;
            A3 += x3 * w3.x; B3 += x3 * w3.y;
        }
        #pragma unroll
        for (int kk = 0; kk < 32; kk += 4) {
            int k = hb + kk;
            int sl = k >> 1;
            float ha0 = __shfl_sync(FULLM, h0, sl);       // h[k]
            float ha1 = __shfl_sync(FULLM, h1, sl);       // h[k+1]
            float hb0 = __shfl_sync(FULLM, h0, sl + 1);   // h[k+2]
            float hb1 = __shfl_sync(FULLM, h1, sl + 1);   // h[k+3]
            float2 w0 = *(const float2*)&s.Whh[(k + 0) * HH + j0];
            float2 w1 = *(const float2*)&s.Whh[(k + 1) * HH + j0];
            float2 w2 = *(const float2*)&s.Whh[(k + 2) * HH + j0];
            float2 w3 = *(const float2*)&s.Whh[(k + 3) * HH + j0];
            A0 += ha0 * w0.x; B0 += ha0 * w0.y;
            A1 += ha1 * w1.x; B1 += ha1 * w1.y;
            A2 += hb0 * w2.x; B2 += hb0 * w2.y;
            A3 += hb1 * w3.x; B3 += hb1 * w3.y;
        }
        s.red[par][w][lane] = make_float2((A0 + A1) + (A2 + A3),
                                          (B0 + B1) + (B2 + B3));
        __syncthreads();
        float2 pa = s.red[par][0][lane];
        float2 pb = s.red[par][1][lane];
        float pre0 = pa.x + pb.x;
        float pre1 = pa.y + pb.y;

        float ho0 = h0 * 0.8f + fmaxf(pre0, 0.f) * 0.2f;
        float ho1 = h1 * 0.8f + fmaxf(pre1, 0.f) * 0.2f;

        if (actc) {   // Kalman correction (both warps, identical)
            float p0 = 0.f, p1 = 0.f, p2 = 0.f;
            #pragma unroll
            for (int sd = 0; sd < NHIST; sd++) {
                float2 w0 = *(const float2*)&s.CW[0 * 320 + sd * 64 + j0];
                float2 w1 = *(const float2*)&s.CW[1 * 320 + sd * 64 + j0];
                float2 w2 = *(const float2*)&s.CW[2 * 320 + sd * 64 + j0];
                float v0 = hh[sd][0], v1 = hh[sd][1];
                p0 += w0.x * v0 + w0.y * v1;
                p1 += w1.x * v0 + w1.y * v1;
                p2 += w2.x * v0 + w2.y * v1;
            }
            p0 -= c0a * ho0 + c0b * ho1;
            p1 -= c1a * ho0 + c1b * ho1;
            p2 -= c2a * ho0 + c2b * ho1;
            #pragma unroll
            for (int off = 16; off; off >>= 1) {
                p0 += __shfl_xor_sync(FULLM, p0, off);
                p1 += __shfl_xor_sync(FULLM, p1, off);
                p2 += __shfl_xor_sync(FULLM, p2, off);
            }
            p0 += cb0; p1 += cb1; p2 += cb2;
            ho0 += kc0.x * p0 + kc1.x * p1 + kc2.x * p2;
            ho1 += kc0.y * p0 + kc1.y * p1 + kc2.y * p2;
        }

        // shift history (registers)
        #pragma unroll
        for (int sd = 0; sd < NHIST - 1; sd++) {
            hh[sd][0] = hh[sd + 1][0]; hh[sd][1] = hh[sd + 1][1];
        }
        hh[NHIST - 1][0] = ho0; hh[NHIST - 1][1] = ho1;

        if (w == 0)
            *(float2*)&out[((size_t)t * BB + row) * HH + j0] = make_float2(ho0, ho1);

        h0 = ho0; h1 = ho1;
        xc = xn; xn = xn2;
        actc = actn; actn = actn2;
        kc0 = kn0; kc1 = kn1; kc2 = kn2;
        par ^= 1;
    }

    if (hlast && w == 0)
        *(float2*)&hlast[(size_t)row * HH + j0] = make_float2(h0, h1);
}

// ======================================================================
extern "C" void kernel_launch(void* const* d_in, const int* in_sizes, int n_in,
                              void* d_out, int out_size) {
    const float* x     = (const float*)d_in[0];
    const float* W_ih  = (const float*)d_in[1];
    const float* b_ih  = (const float*)d_in[2];
    const float* W_hh  = (const float*)d_in[3];
    const float* b_hh  = (const float*)d_in[4];
    const float* C     = (const float*)d_in[5];
    const float* W_mlp = (const float*)d_in[6];
    const float* b_mlp = (const float*)d_in[7];
    float* out = (float*)d_out;

    const long long main_elems = (long long)TT * BB * HH;
    float* hlast = ((long long)out_size >= main_elems + (long long)BB * HH)
                       ? out + main_elems : nullptr;

    cudaFuncSetAttribute(cov_kernel, cudaFuncAttributeMaxDynamicSharedMemorySize,
                         (int)sizeof(PSmem));
    cudaFuncSetAttribute(seq_kernel, cudaFuncAttributeMaxDynamicSharedMemorySize,
                         (int)sizeof(CSmem));

    cov_kernel<<<1, 256, sizeof(PSmem)>>>(W_hh, C, W_mlp, b_mlp);
    seq_kernel<<<BB, 64, sizeof(CSmem)>>>(x, W_ih, b_ih, W_hh, b_hh, C, out, hlast);
}

// round 9
// speedup vs baseline: 1.4411x; 1.4411x over previous
#include <cuda_runtime.h>
#include <cstdint>

#define TT 1000
#define BB 512
#define IDM 32
#define HH 64
#define NHIST 5
#define FULLM 0xffffffffu

// Kalman gains per step: layout [t][o*64 + i]
__device__ __align__(16) float g_U[TT * 192];
// per-step "correction active" flag (0 => K_t == 0, skip correction)
__device__ int g_act[TT];
// CW = C @ W_mlp  (3 x 320), Cb = C @ b_mlp (3)
__device__ __align__(16) float g_CW[3 * 320];
__device__ __align__(16) float g_Cb[4];

// ---- packed f32x2 helpers (Blackwell FFMA2 path, PTX-only) ----
__device__ __forceinline__ void fma2(unsigned long long& d,
                                     unsigned long long a,
                                     unsigned long long b) {
    asm("fma.rn.f32x2 %0, %1, %2, %0;" : "+l"(d) : "l"(a), "l"(b));
}
__device__ __forceinline__ unsigned long long pack2(float lo, float hi) {
    unsigned long long r;
    asm("mov.b64 %0, {%1, %2};" : "=l"(r) : "f"(lo), "f"(hi));
    return r;
}
__device__ __forceinline__ float2 unpack2(unsigned long long v) {
    float2 r;
    asm("mov.b64 {%0, %1}, %2;" : "=f"(r.x), "=f"(r.y) : "l"(v));
    return r;
}

// ======================================================================
// Producer: prep (CW fold) + Riccati chain -> K_t. Single block.
// Exit when max|K| <= 1e-6 (K->0 geometrically); zero-fill tail.
// ======================================================================
#define PD 66   // even => 8B-aligned float2 rows; padded => clean banks

struct PSmem {
    float A[64 * PD];
    float At[64 * PD];
    float cov[64 * PD];
    float E[64 * PD];
    float P[64 * PD];
    float Cs[192];
    float Y[64 * 3];
    float S[9];
    float Si[9];
    float U[192];
    float Up[192];
    float CP[192];
    int ctl[2];
    int done;      // 0 = continue, 1 = tail<-U (stationary), 2 = tail<-0
};

__global__ void __launch_bounds__(256, 1)
cov_kernel(const float* __restrict__ W_hh, const float* __restrict__ Cmat,
           const float* __restrict__ W_mlp, const float* __restrict__ b_mlp) {
    extern __shared__ char praw[];
    PSmem& s = *reinterpret_cast<PSmem*>(praw);
    const int tid = threadIdx.x;

    // ---- prep: CW = C @ W_mlp, Cb = C @ b_mlp, g_act init ----
    for (int idx = tid; idx < 960; idx += 256) {
        int o = idx / 320, m = idx - o * 320;
        float acc = 0.f;
        #pragma unroll 8
        for (int j = 0; j < 64; j++) acc += Cmat[o * 64 + j] * W_mlp[j * 320 + m];
        g_CW[idx] = acc;
    }
    if (tid < 3) {
        float acc = 0.f;
        for (int j = 0; j < 64; j++) acc += Cmat[tid * 64 + j] * b_mlp[j];
        g_Cb[tid] = acc;
    }
    if (tid >= 8 && tid < 8 + NHIST) g_act[tid - 8] = 0;

    for (int idx = tid; idx < 4096; idx += 256) {
        int i = idx >> 6, k = idx & 63;
        float v = W_hh[idx];
        s.A[i * PD + k]  = v;
        s.At[k * PD + i] = v;
        s.cov[i * PD + k] = (i == k) ? 1.f : 0.f;
    }
    for (int idx = tid; idx < 192; idx += 256) { s.Cs[idx] = Cmat[idx]; s.Up[idx] = 0.f; }
    if (tid < 2) s.ctl[tid] = 0;
    if (tid == 0) s.done = 0;
    __syncthreads();

    const int ty = tid >> 4;
    const int tx = tid & 15;

    for (int t = NHIST; t < TT; t++) {
        // ---- E = A @ cov  (f32x2) ----
        {
            unsigned long long c01[4] = {0, 0, 0, 0};
            unsigned long long c23[4] = {0, 0, 0, 0};
            #pragma unroll 4
            for (int k = 0; k < 64; k++) {
                unsigned long long b01 =
                    *(const unsigned long long*)&s.cov[k * PD + tx * 4];
                unsigned long long b23 =
                    *(const unsigned long long*)&s.cov[k * PD + tx * 4 + 2];
                #pragma unroll
                for (int r = 0; r < 4; r++) {
                    float av = s.A[(ty * 4 + r) * PD + k];
                    unsigned long long ap = pack2(av, av);
                    fma2(c01[r], ap, b01);
                    fma2(c23[r], ap, b23);
                }
            }
            #pragma unroll
            for (int r = 0; r < 4; r++) {
                *(float2*)&s.E[(ty * 4 + r) * PD + tx * 4]     = unpack2(c01[r]);
                *(float2*)&s.E[(ty * 4 + r) * PD + tx * 4 + 2] = unpack2(c23[r]);
            }
        }
        __syncthreads();

        // ---- P = E @ A^T ----
        {
            unsigned long long c01[4] = {0, 0, 0, 0};
            unsigned long long c23[4] = {0, 0, 0, 0};
            #pragma unroll 4
            for (int k = 0; k < 64; k++) {
                unsigned long long b01 =
                    *(const unsigned long long*)&s.At[k * PD + tx * 4];
                unsigned long long b23 =
                    *(const unsigned long long*)&s.At[k * PD + tx * 4 + 2];
                #pragma unroll
                for (int r = 0; r < 4; r++) {
                    float av = s.E[(ty * 4 + r) * PD + k];
                    unsigned long long ap = pack2(av, av);
                    fma2(c01[r], ap, b01);
                    fma2(c23[r], ap, b23);
                }
            }
            #pragma unroll
            for (int r = 0; r < 4; r++) {
                *(float2*)&s.P[(ty * 4 + r) * PD + tx * 4]     = unpack2(c01[r]);
                *(float2*)&s.P[(ty * 4 + r) * PD + tx * 4 + 2] = unpack2(c23[r]);
            }
        }
        __syncthreads();

        // ---- Y = P @ C^T (64x3) ----
        if (tid < 192) {
            int o = tid >> 6, i = tid & 63;
            float acc = 0.f;
            for (int k = 0; k < 64; k++) acc += s.P[i * PD + k] * s.Cs[o * 64 + k];
            s.Y[i * 3 + o] = acc;
        }
        __syncthreads();

        // ---- S = C @ Y + I ----
        if (tid < 9) {
            int o1 = tid / 3, o2 = tid - o1 * 3;
            float acc = (o1 == o2) ? 1.f : 0.f;
            for (int k = 0; k < 64; k++) acc += s.Cs[o1 * 64 + k] * s.Y[k * 3 + o2];
            s.S[tid] = acc;
        }
        __syncthreads();

        // ---- Si = inv(S) ----
        if (tid == 0) {
            float a = s.S[0], b = s.S[1], c = s.S[2];
            float d = s.S[3], e = s.S[4], f = s.S[5];
            float g = s.S[6], h = s.S[7], i2 = s.S[8];
            float A0 =  (e * i2 - f * h);
            float A1 = -(d * i2 - f * g);
            float A2 =  (d * h  - e * g);
            float B0 = -(b * i2 - c * h);
            float B1 =  (a * i2 - c * g);
            float B2 = -(a * h  - b * g);
            float C0 =  (b * f - c * e);
            float C1 = -(a * f - c * d);
            float C2 =  (a * e - b * d);
            float det = a * A0 + b * A1 + c * A2;
            float id = 1.f / det;
            s.Si[0] = A0 * id; s.Si[1] = B0 * id; s.Si[2] = C0 * id;
            s.Si[3] = A1 * id; s.Si[4] = B1 * id; s.Si[5] = C1 * id;
            s.Si[6] = A2 * id; s.Si[7] = B2 * id; s.Si[8] = C2 * id;
        }
        __syncthreads();

        // ---- U = Y @ Si (K), store, track magnitude + delta ----
        if (tid < 192) {
            int o = tid >> 6, i = tid & 63;
            float u = s.Y[i * 3 + 0] * s.Si[0 + o]
                    + s.Y[i * 3 + 1] * s.Si[3 + o]
                    + s.Y[i * 3 + 2] * s.Si[6 + o];
            s.U[tid] = u;
            g_U[t * 192 + tid] = u;
            float dd = fabsf(u - s.Up[tid]);
            s.Up[tid] = u;
            atomicMax(&s.ctl[0], __float_as_int(dd));
            atomicMax(&s.ctl[1], __float_as_int(fabsf(u)));
        }
        if (tid == 200) g_act[t] = 1;
        __syncthreads();

        // ---- CP = C @ P, exit decision ----
        if (tid < 192) {
            int o = tid >> 6, j = tid & 63;
            float acc = 0.f;
            for (int k = 0; k < 64; k++) acc += s.Cs[o * 64 + k] * s.P[k * PD + j];
            s.CP[tid] = acc;
        }
        if (tid == 0) {
            float md = __int_as_float(s.ctl[0]);
            float ma = __int_as_float(s.ctl[1]);
            if (ma <= 1e-6f)            s.done = 2;  // K negligible: tail = h_obs
            else if (md <= 1e-6f * ma)  s.done = 1;  // K stationary (nonzero)
            s.ctl[0] = 0; s.ctl[1] = 0;
        }
        __syncthreads();

        // ---- cov = P - U^T CP ----
        for (int e = tid; e < 4096; e += 256) {
            int i = e >> 6, j = e & 63;
            s.cov[i * PD + j] = s.P[i * PD + j]
                - (s.U[i]       * s.CP[j]
                 + s.U[64 + i]  * s.CP[64 + j]
                 + s.U[128 + i] * s.CP[128 + j]);
        }
        __syncthreads();

        if (s.done) {
            const int dz = (s.done == 2);
            for (int tt = t + 1; tt < TT; tt++) {
                for (int idx = tid; idx < 192; idx += 256)
                    g_U[tt * 192 + idx] = dz ? 0.f : s.U[idx];
                if (tid == 200) g_act[tt] = dz ? 0 : 1;
            }
            break;
        }
    }
}

// ======================================================================
// Consumer: block = 64 threads = 1 batch row; lane owns output dim
// j = tid. Weights register-stationary (persistent-RNN); per-step smem
// traffic is broadcast-only (h + x). One __syncthreads per step.
// ======================================================================
__global__ void __launch_bounds__(64, 1)
seq_kernel(const float* __restrict__ x,
           const float* __restrict__ W_ih, const float* __restrict__ b_ih,
           const float* __restrict__ W_hh, const float* __restrict__ b_hh,
           const float* __restrict__ C,
           float* __restrict__ out, float* __restrict__ hlast) {
    __shared__ __align__(16) float sh[2][64];   // parity-buffered hidden
    __shared__ __align__(16) float sx[2][32];   // parity-buffered x
    __shared__ float sred[2][4];                // correction warp partials

    const int tid  = threadIdx.x;
    const int w    = tid >> 5;
    const int lane = tid & 31;
    const int j    = tid;          // output dim owned by this lane
    const int row  = blockIdx.x;

    // ---- weights into registers (f32x2-packed) ----
    unsigned long long whh[32], wih[16];
    #pragma unroll
    for (int p = 0; p < 32; p++)
        whh[p] = *(const unsigned long long*)&W_hh[j * HH + 2 * p];
    #pragma unroll
    for (int p = 0; p < 16; p++)
        wih[p] = *(const unsigned long long*)&W_ih[j * IDM + 2 * p];

    const float Cj0 = C[j], Cj1 = C[64 + j], Cj2 = C[128 + j];
    const float bj  = b_ih[j] + b_hh[j];
    const float cb0 = g_Cb[0], cb1 = g_Cb[1], cb2 = g_Cb[2];

    // ---- init state ----
    sh[0][j] = 0.f;
    float hcur = 0.f;
    float hist[NHIST] = {0.f, 0.f, 0.f, 0.f, 0.f};
    float xn1 = 0.f, xn2 = 0.f;
    if (w == 0) {
        sx[0][lane] = x[(size_t)row * IDM + lane];
        xn1 = x[((size_t)1 * BB + row) * IDM + lane];
        xn2 = x[((size_t)2 * BB + row) * IDM + lane];
    }
    int actc = 0, actn = 0;     // g_act[0], g_act[1] known 0
    float k0 = 0.f, k1 = 0.f, k2 = 0.f;
    int par = 0;
    __syncthreads();

    for (int t = 0; t < TT; t++) {
        // ---- prefetch x[t+3], act[t+2], K[t+1] ----
        float xn3 = 0.f;
        if (w == 0 && t + 3 < TT)
            xn3 = x[((size_t)(t + 3) * BB + row) * IDM + lane];
        int actn2 = (t + 2 < TT) ? g_act[t + 2] : 0;
        float kn0 = 0.f, kn1 = 0.f, kn2 = 0.f;
        if (actn) {
            const float* Ut = &g_U[(size_t)(t + 1) * 192];
            kn0 = Ut[j]; kn1 = Ut[64 + j]; kn2 = Ut[128 + j];
        }

        // ---- GEMV: broadcast reads, register weights, FFMA2 ----
        unsigned long long a0 = 0, a1 = 0, a2 = 0, a3 = 0;
        const ulonglong2* hp = (const ulonglong2*)sh[par];
        #pragma unroll
        for (int q = 0; q < 16; q++) {
            ulonglong2 hv = hp[q];               // h[4q..4q+3]
            if (q & 1) { fma2(a2, hv.x, whh[2 * q]); fma2(a3, hv.y, whh[2 * q + 1]); }
            else       { fma2(a0, hv.x, whh[2 * q]); fma2(a1, hv.y, whh[2 * q + 1]); }
        }
        const ulonglong2* xp = (const ulonglong2*)sx[par];
        #pragma unroll
        for (int q = 0; q < 8; q++) {
            ulonglong2 xv = xp[q];               // x[4q..4q+3]
            if (q & 1) { fma2(a2, xv.x, wih[2 * q]); fma2(a3, xv.y, wih[2 * q + 1]); }
            else       { fma2(a0, xv.x, wih[2 * q]); fma2(a1, xv.y, wih[2 * q + 1]); }
        }
        float2 A0 = unpack2(a0), A1 = unpack2(a1), A2 = unpack2(a2), A3 = unpack2(a3);
        float pre = bj + (((A0.x + A0.y) + (A1.x + A1.y))
                        + ((A2.x + A2.y) + (A3.x + A3.y)));
        float ho = hcur * 0.8f + fmaxf(pre, 0.f) * 0.2f;

        // ---- Kalman correction (rarely active) ----
        if (actc) {
            // per-lane partials of p_o = CW.hist + Cb - C.h_obs
            float p0 = -Cj0 * ho, p1 = -Cj1 * ho, p2 = -Cj2 * ho;
            #pragma unroll
            for (int sd = 0; sd < NHIST; sd++) {
                float hv = hist[sd];
                p0 += g_CW[0 * 320 + sd * 64 + j] * hv;
                p1 += g_CW[1 * 320 + sd * 64 + j] * hv;
                p2 += g_CW[2 * 320 + sd * 64 + j] * hv;
            }
            #pragma unroll
            for (int off = 16; off; off >>= 1) {
                p0 += __shfl_xor_sync(FULLM, p0, off);
                p1 += __shfl_xor_sync(FULLM, p1, off);
                p2 += __shfl_xor_sync(FULLM, p2, off);
            }
            if (lane == 0) {
                sred[w][0] = p0; sred[w][1] = p1; sred[w][2] = p2;
            }
            __syncthreads();
            p0 = sred[0][0] + sred[1][0] + cb0;
            p1 = sred[0][1] + sred[1][1] + cb1;
            p2 = sred[0][2] + sred[1][2] + cb2;
            ho += k0 * p0 + k1 * p1 + k2 * p2;
        }

        // ---- history shift (registers) ----
        #pragma unroll
        for (int sd = 0; sd < NHIST - 1; sd++) hist[sd] = hist[sd + 1];
        hist[NHIST - 1] = ho;

        // ---- publish state, write output, advance pipeline ----
        sh[par ^ 1][j] = ho;
        if (w == 0) sx[par ^ 1][lane] = xn1;
        out[((size_t)t * BB + row) * HH + j] = ho;
        __syncthreads();

        hcur = ho;
        xn1 = xn2; xn2 = xn3;
        actc = actn; actn = actn2;
        k0 = kn0; k1 = kn1; k2 = kn2;
        par ^= 1;
    }

    if (hlast) hlast[(size_t)row * HH + j] = hcur;
}

// ======================================================================
extern "C" void kernel_launch(void* const* d_in, const int* in_sizes, int n_in,
                              void* d_out, int out_size) {
    const float* x     = (const float*)d_in[0];
    const float* W_ih  = (const float*)d_in[1];
    const float* b_ih  = (const float*)d_in[2];
    const float* W_hh  = (const float*)d_in[3];
    const float* b_hh  = (const float*)d_in[4];
    const float* C     = (const float*)d_in[5];
    const float* W_mlp = (const float*)d_in[6];
    const float* b_mlp = (const float*)d_in[7];
    float* out = (float*)d_out;

    const long long main_elems = (long long)TT * BB * HH;
    float* hlast = ((long long)out_size >= main_elems + (long long)BB * HH)
                       ? out + main_elems : nullptr;

    cudaFuncSetAttribute(cov_kernel, cudaFuncAttributeMaxDynamicSharedMemorySize,
                         (int)sizeof(PSmem));

    cov_kernel<<<1, 256, sizeof(PSmem)>>>(W_hh, C, W_mlp, b_mlp);
    seq_kernel<<<BB, 64>>>(x, W_ih, b_ih, W_hh, b_hh, C, out, hlast);
}